// round 7
// baseline (speedup 1.0000x reference)
#include <cuda_runtime.h>

#define KNBR     16
#define C        128
#define ROWS     32768
#define TM       32              // rows per stage
#define THREADS  256             // warps 0-3 producer, 4-7 consumer
#define NTILES   (ROWS / TM)     // 1024
#define GRID     304             // 2 blocks/SM

#define HT_FLOATS (C * TM)       // transposed h stage: 128c x 32m
#define SMEM_FLOATS (C * C + 2 * HT_FLOATS)
#define SMEM_BYTES  (SMEM_FLOATS * 4)   // 96 KB

typedef unsigned long long u64;

__device__ __forceinline__ u64 fma2(u64 a, u64 b, u64 c) {
    u64 d; asm("fma.rn.f32x2 %0, %1, %2, %3;" : "=l"(d) : "l"(a), "l"(b), "l"(c)); return d;
}
__device__ __forceinline__ u64 add2(u64 a, u64 b) {
    u64 d; asm("add.rn.f32x2 %0, %1, %2;" : "=l"(d) : "l"(a), "l"(b)); return d;
}
__device__ __forceinline__ u64 mul2(u64 a, u64 b) {
    u64 d; asm("mul.rn.f32x2 %0, %1, %2;" : "=l"(d) : "l"(a), "l"(b)); return d;
}
__device__ __forceinline__ u64 rep2(float v) {
    u64 d; asm("mov.b64 %0, {%1, %1};" : "=l"(d) : "f"(v)); return d;
}
__device__ __forceinline__ float2 unpack2(u64 v) {
    float2 r; asm("mov.b64 {%0, %1}, %2;" : "=f"(r.x), "=f"(r.y) : "l"(v)); return r;
}
// 192-count named barriers: producer contributes 128, the stage's warp-pair 64.
__device__ __forceinline__ void bar_sync192(int id) {
    asm volatile("bar.sync %0, 192;" :: "r"(id) : "memory");
}
__device__ __forceinline__ void bar_arrive192(int id) {
    asm volatile("bar.arrive %0, 192;" :: "r"(id) : "memory");
}
#define FULLB(s)  (1 + 2 * (s))
#define EMPTYB(s) (2 + 2 * (s))

__global__ __launch_bounds__(THREADS, 2)
void gin_fused_kernel(const float* __restrict__ x,
                      const void* __restrict__ ei_raw,
                      const float* __restrict__ W,
                      const float* __restrict__ bias,
                      const float* __restrict__ epsp,
                      float* __restrict__ out)
{
    extern __shared__ float smem[];
    float* sWt  = smem;                 // 128x128 : W^T [c][o]
    float* hbuf = smem + C * C;         // 2 stages x HT_FLOATS
    float* stg  = hbuf;                 // alias: 32x33 transpose staging

    const int tid = threadIdx.x;

    // ---------- dtype sniff: int64 (odd words all 0) vs int32 ----------
    const int* w32 = (const int*)ei_raw;
    int orv = 0;
    #pragma unroll
    for (int t = 0; t < 64; t++) orv |= w32[t * 8192 + 1];
    const bool is64 = (orv == 0);
    const long long* w64 = (const long long*)ei_raw;

    // ---------- one-time: transpose W into sWt[c][o], 16 tiles of 32x32 ----------
    {
        const int trow = tid >> 5;      // 0..7
        const int tcol = tid & 31;
        for (int t = 0; t < 16; t++) {
            const int bi = t >> 2, bj = t & 3;
            #pragma unroll
            for (int rr = 0; rr < 4; rr++)
                stg[(trow + 8 * rr) * 33 + tcol] =
                    W[(size_t)(bi * 32 + trow + 8 * rr) * C + bj * 32 + tcol];
            __syncthreads();
            #pragma unroll
            for (int rr = 0; rr < 4; rr++)
                sWt[(size_t)(bj * 32 + trow + 8 * rr) * C + bi * 32 + tcol] =
                    stg[tcol * 33 + trow + 8 * rr];
            __syncthreads();
        }
    }

    const float oe  = 1.0f + epsp[0];
    const u64   oe2 = rep2(oe);
    const int wid = tid >> 5;

    if (wid < 4) {
        // =================== PRODUCER: warps 0-3 ===================
        const int rl = tid >> 3;        // 0..15 : rows rl and rl+16
        const int p  = tid & 7;         // 16B slice within 128B line
        const int X4 = 4 * p;

        int iter = 0;
        for (int tile = blockIdx.x; tile < NTILES; tile += GRID, iter++) {
            const int s = iter & 1;
            const int row0 = tile * TM;
            float* sh = hbuf + s * HT_FLOATS;

            if (iter >= 2) bar_sync192(EMPTYB(s));   // stage s consumed?

            #pragma unroll
            for (int hh = 0; hh < 2; hh++) {
                const int lrow = rl + 16 * hh;
                const int row  = row0 + lrow;
                const int bbase = (row >> 13) << 13;     // b * 8192
                const int msw = lrow ^ X4;               // swizzled m

                int idxs[KNBR];
                if (!is64) {
                    const int4* ip = (const int4*)(w32 + (size_t)row * KNBR);
                    #pragma unroll
                    for (int q = 0; q < 4; q++) {
                        int4 v = ip[q];
                        idxs[4*q+0] = v.x; idxs[4*q+1] = v.y;
                        idxs[4*q+2] = v.z; idxs[4*q+3] = v.w;
                    }
                } else {
                    #pragma unroll
                    for (int k = 0; k < KNBR; k++)
                        idxs[k] = (int)w64[(size_t)row * KNBR + k];
                }
                #pragma unroll
                for (int k = 0; k < KNBR; k++)
                    idxs[k] = (bbase + idxs[k]) << 7;

                const float* xs = x + ((size_t)row << 7) + 4 * p;
                u64 a[8];
                #pragma unroll
                for (int j = 0; j < 4; j++) {
                    ulonglong2 v = *(const ulonglong2*)(xs + 32 * j);
                    a[2*j]   = mul2(v.x, oe2);
                    a[2*j+1] = mul2(v.y, oe2);
                }
                #pragma unroll 4
                for (int k = 0; k < KNBR; k++) {
                    const float* xn = x + idxs[k] + 4 * p;
                    #pragma unroll
                    for (int j = 0; j < 4; j++) {
                        ulonglong2 v = *(const ulonglong2*)(xn + 32 * j);
                        a[2*j]   = add2(a[2*j],   v.x);
                        a[2*j+1] = add2(a[2*j+1], v.y);
                    }
                }
                #pragma unroll
                for (int j = 0; j < 4; j++) {
                    const int cb = 32 * j + 4 * p;
                    float2 f0 = unpack2(a[2*j]);
                    float2 f1 = unpack2(a[2*j+1]);
                    sh[((cb + 0) << 5) + msw] = f0.x;
                    sh[((cb + 1) << 5) + msw] = f0.y;
                    sh[((cb + 2) << 5) + msw] = f1.x;
                    sh[((cb + 3) << 5) + msw] = f1.y;
                }
            }
            bar_arrive192(FULLB(s));     // stage s full
        }
    } else {
        // =================== CONSUMER: warps 4-7 ===================
        // warp-pair (4,5) owns stage 0; (6,7) owns stage 1.
        // each warp: 16 rows x 128 cols (4 cols/thread, 16 rows/thread).
        const int cwid = wid - 4;
        const int s    = cwid >> 1;          // stage this warp serves
        const int r0_  = (cwid & 1) << 4;    // 0 or 16: row half within stage
        const int lane = tid & 31;
        float* sh = hbuf + s * HT_FLOATS;

        const float4 b4 = *(const float4*)(bias + 4 * lane);

        for (int tile = blockIdx.x + s * GRID; tile < NTILES; tile += 2 * GRID) {
            bar_sync192(FULLB(s));           // wait stage full

            u64 acc[4][8];
            #pragma unroll
            for (int q = 0; q < 4; q++)
                #pragma unroll
                for (int j = 0; j < 8; j++) acc[q][j] = 0ull;

            #pragma unroll 2
            for (int c = 0; c < C; c++) {
                float4 w4 = *(const float4*)(sWt + (c << 7) + 4 * lane);
                const int X = c & 0x1C;
                const float* hc = sh + (c << 5);
                ulonglong2 h0 = *(const ulonglong2*)(hc + ((r0_ + 0)  ^ X));
                ulonglong2 h1 = *(const ulonglong2*)(hc + ((r0_ + 4)  ^ X));
                ulonglong2 h2 = *(const ulonglong2*)(hc + ((r0_ + 8)  ^ X));
                ulonglong2 h3 = *(const ulonglong2*)(hc + ((r0_ + 12) ^ X));
                u64 q0 = rep2(w4.x), q1 = rep2(w4.y), q2 = rep2(w4.z), q3 = rep2(w4.w);
                acc[0][0] = fma2(q0, h0.x, acc[0][0]);
                acc[0][1] = fma2(q0, h0.y, acc[0][1]);
                acc[0][2] = fma2(q0, h1.x, acc[0][2]);
                acc[0][3] = fma2(q0, h1.y, acc[0][3]);
                acc[0][4] = fma2(q0, h2.x, acc[0][4]);
                acc[0][5] = fma2(q0, h2.y, acc[0][5]);
                acc[0][6] = fma2(q0, h3.x, acc[0][6]);
                acc[0][7] = fma2(q0, h3.y, acc[0][7]);
                acc[1][0] = fma2(q1, h0.x, acc[1][0]);
                acc[1][1] = fma2(q1, h0.y, acc[1][1]);
                acc[1][2] = fma2(q1, h1.x, acc[1][2]);
                acc[1][3] = fma2(q1, h1.y, acc[1][3]);
                acc[1][4] = fma2(q1, h2.x, acc[1][4]);
                acc[1][5] = fma2(q1, h2.y, acc[1][5]);
                acc[1][6] = fma2(q1, h3.x, acc[1][6]);
                acc[1][7] = fma2(q1, h3.y, acc[1][7]);
                acc[2][0] = fma2(q2, h0.x, acc[2][0]);
                acc[2][1] = fma2(q2, h0.y, acc[2][1]);
                acc[2][2] = fma2(q2, h1.x, acc[2][2]);
                acc[2][3] = fma2(q2, h1.y, acc[2][3]);
                acc[2][4] = fma2(q2, h2.x, acc[2][4]);
                acc[2][5] = fma2(q2, h2.y, acc[2][5]);
                acc[2][6] = fma2(q2, h3.x, acc[2][6]);
                acc[2][7] = fma2(q2, h3.y, acc[2][7]);
                acc[3][0] = fma2(q3, h0.x, acc[3][0]);
                acc[3][1] = fma2(q3, h0.y, acc[3][1]);
                acc[3][2] = fma2(q3, h1.x, acc[3][2]);
                acc[3][3] = fma2(q3, h1.y, acc[3][3]);
                acc[3][4] = fma2(q3, h2.x, acc[3][4]);
                acc[3][5] = fma2(q3, h2.y, acc[3][5]);
                acc[3][6] = fma2(q3, h3.x, acc[3][6]);
                acc[3][7] = fma2(q3, h3.y, acc[3][7]);
            }
            bar_arrive192(EMPTYB(s));        // stage free (acc lives in regs)

            const int rowb = tile * TM + r0_;
            #pragma unroll
            for (int j = 0; j < 8; j++) {
                float2 a0 = unpack2(acc[0][j]);
                float2 a1 = unpack2(acc[1][j]);
                float2 a2 = unpack2(acc[2][j]);
                float2 a3 = unpack2(acc[3][j]);
                float4 o0, o1;
                o0.x = fmaxf(a0.x + b4.x, 0.f);
                o0.y = fmaxf(a1.x + b4.y, 0.f);
                o0.z = fmaxf(a2.x + b4.z, 0.f);
                o0.w = fmaxf(a3.x + b4.w, 0.f);
                o1.x = fmaxf(a0.y + b4.x, 0.f);
                o1.y = fmaxf(a1.y + b4.y, 0.f);
                o1.z = fmaxf(a2.y + b4.z, 0.f);
                o1.w = fmaxf(a3.y + b4.w, 0.f);
                const size_t rbase = (size_t)(rowb + 2 * j) * C + 4 * lane;
                *(float4*)(out + rbase)     = o0;
                *(float4*)(out + rbase + C) = o1;
            }
        }
    }
}

extern "C" void kernel_launch(void* const* d_in, const int* in_sizes, int n_in,
                              void* d_out, int out_size)
{
    const float* x    = (const float*)d_in[0];
    const void*  ei   = d_in[1];
    const float* W    = (const float*)d_in[2];
    const float* bias = (const float*)d_in[3];
    const float* eps  = (const float*)d_in[4];
    float*       out  = (float*)d_out;

    cudaFuncSetAttribute(gin_fused_kernel,
                         cudaFuncAttributeMaxDynamicSharedMemorySize, SMEM_BYTES);

    gin_fused_kernel<<<GRID, THREADS, SMEM_BYTES>>>(x, ei, W, bias, eps, out);
}

// round 8
// speedup vs baseline: 1.0999x; 1.0999x over previous
#include <cuda_runtime.h>

#define KNBR     16
#define C        128
#define ROWS     32768
#define TM       32              // rows per stage
#define THREADS  384             // warps 0-7 producer, 8-11 consumer
#define NTILES   (ROWS / TM)     // 1024
#define GRID     304             // 2 blocks/SM

#define HT_FLOATS (C * TM)       // transposed h stage: 128c x 32m
#define SMEM_FLOATS (C * C + 2 * HT_FLOATS)
#define SMEM_BYTES  (SMEM_FLOATS * 4)   // 96 KB

typedef unsigned long long u64;

__device__ __forceinline__ u64 fma2(u64 a, u64 b, u64 c) {
    u64 d; asm("fma.rn.f32x2 %0, %1, %2, %3;" : "=l"(d) : "l"(a), "l"(b), "l"(c)); return d;
}
__device__ __forceinline__ u64 add2(u64 a, u64 b) {
    u64 d; asm("add.rn.f32x2 %0, %1, %2;" : "=l"(d) : "l"(a), "l"(b)); return d;
}
__device__ __forceinline__ u64 mul2(u64 a, u64 b) {
    u64 d; asm("mul.rn.f32x2 %0, %1, %2;" : "=l"(d) : "l"(a), "l"(b)); return d;
}
__device__ __forceinline__ u64 rep2(float v) {
    u64 d; asm("mov.b64 %0, {%1, %1};" : "=l"(d) : "f"(v)); return d;
}
__device__ __forceinline__ float2 unpack2(u64 v) {
    float2 r; asm("mov.b64 {%0, %1}, %2;" : "=f"(r.x), "=f"(r.y) : "l"(v)); return r;
}
__device__ __forceinline__ void bar_sync(int id) {
    asm volatile("bar.sync %0, 384;" :: "r"(id) : "memory");
}
__device__ __forceinline__ void bar_arrive(int id) {
    asm volatile("bar.arrive %0, 384;" :: "r"(id) : "memory");
}

__global__ __launch_bounds__(THREADS, 2)
void gin_fused_kernel(const float* __restrict__ x,
                      const void* __restrict__ ei_raw,
                      const float* __restrict__ W,
                      const float* __restrict__ bias,
                      const float* __restrict__ epsp,
                      float* __restrict__ out)
{
    extern __shared__ float smem[];
    float* sWt  = smem;                 // 128x128 : W^T [c][o]
    float* hbuf = smem + C * C;         // 2 stages x HT_FLOATS
    float* stg  = hbuf;                 // alias: 32x33 transpose staging

    const int tid = threadIdx.x;

    // ---------- dtype sniff: int64 (odd words all 0) vs int32 ----------
    const int* w32 = (const int*)ei_raw;
    int orv = 0;
    #pragma unroll
    for (int t = 0; t < 64; t++) orv |= w32[t * 8192 + 1];
    const bool is64 = (orv == 0);
    const long long* w64 = (const long long*)ei_raw;

    // ---------- one-time: transpose W into sWt[c][o], 16 tiles of 32x32 ----------
    {
        const int trow = tid >> 5;      // 0..11
        const int tcol = tid & 31;
        for (int t = 0; t < 16; t++) {
            const int bi = t >> 2, bj = t & 3;
            if (trow < 8) {
                #pragma unroll
                for (int rr = 0; rr < 4; rr++)
                    stg[(trow + 8 * rr) * 33 + tcol] =
                        W[(size_t)(bi * 32 + trow + 8 * rr) * C + bj * 32 + tcol];
            }
            __syncthreads();
            if (trow < 8) {
                #pragma unroll
                for (int rr = 0; rr < 4; rr++)
                    sWt[(size_t)(bj * 32 + trow + 8 * rr) * C + bi * 32 + tcol] =
                        stg[tcol * 33 + trow + 8 * rr];
            }
            __syncthreads();
        }
    }

    const float oe  = 1.0f + epsp[0];
    const u64   oe2 = rep2(oe);

    if (tid < 256) {
        // =================== PRODUCER: warps 0-7, 32 rows in one pass ===================
        const int rl = tid >> 3;        // 0..31 : row within tile
        const int p  = tid & 7;         // 16B slice within 128B line
        const int X4 = 4 * p;
        const int msw = rl ^ X4;        // swizzled m (conflict-free)

        int iter = 0;
        for (int tile = blockIdx.x; tile < NTILES; tile += GRID, iter++) {
            const int s = iter & 1;
            const int row  = tile * TM + rl;
            const int bbase = (row >> 13) << 13;     // b * 8192
            float* sh = hbuf + s * HT_FLOATS;

            if (iter >= 2) bar_sync(3 + s);          // stage s consumed?

            int idxs[KNBR];
            if (!is64) {
                const int4* ip = (const int4*)(w32 + (size_t)row * KNBR);
                #pragma unroll
                for (int q = 0; q < 4; q++) {
                    int4 v = ip[q];
                    idxs[4*q+0] = v.x; idxs[4*q+1] = v.y;
                    idxs[4*q+2] = v.z; idxs[4*q+3] = v.w;
                }
            } else {
                #pragma unroll
                for (int k = 0; k < KNBR; k++)
                    idxs[k] = (int)w64[(size_t)row * KNBR + k];
            }
            #pragma unroll
            for (int k = 0; k < KNBR; k++)
                idxs[k] = (bbase + idxs[k]) << 7;

            const float* xs = x + ((size_t)row << 7) + 4 * p;
            u64 a[8];
            #pragma unroll
            for (int j = 0; j < 4; j++) {
                ulonglong2 v = *(const ulonglong2*)(xs + 32 * j);
                a[2*j]   = mul2(v.x, oe2);
                a[2*j+1] = mul2(v.y, oe2);
            }
            #pragma unroll 4
            for (int k = 0; k < KNBR; k++) {
                const float* xn = x + idxs[k] + 4 * p;
                #pragma unroll
                for (int j = 0; j < 4; j++) {
                    ulonglong2 v = *(const ulonglong2*)(xn + 32 * j);
                    a[2*j]   = add2(a[2*j],   v.x);
                    a[2*j+1] = add2(a[2*j+1], v.y);
                }
            }
            #pragma unroll
            for (int j = 0; j < 4; j++) {
                const int cb = 32 * j + 4 * p;
                float2 f0 = unpack2(a[2*j]);
                float2 f1 = unpack2(a[2*j+1]);
                sh[((cb + 0) << 5) + msw] = f0.x;
                sh[((cb + 1) << 5) + msw] = f0.y;
                sh[((cb + 2) << 5) + msw] = f1.x;
                sh[((cb + 3) << 5) + msw] = f1.y;
            }
            bar_arrive(1 + s);           // stage s full
        }
    } else {
        // =================== CONSUMER: warps 8-11, 8 rows x 128 cols each ===================
        const int ct  = tid - 256;
        const int ty8 = (ct >> 5) << 3;     // row base 0/8/16/24
        const int tx  = ct & 31;            // cols 4tx..4tx+3

        const float4 b4 = *(const float4*)(bias + 4 * tx);

        int iter = 0;
        for (int tile = blockIdx.x; tile < NTILES; tile += GRID, iter++) {
            const int s = iter & 1;
            const int row0 = tile * TM;
            float* sh = hbuf + s * HT_FLOATS;

            bar_sync(1 + s);                // wait stage full

            u64 acc[4][4];                  // [col][row-pair]
            #pragma unroll
            for (int i = 0; i < 4; i++)
                #pragma unroll
                for (int j = 0; j < 4; j++) acc[i][j] = 0ull;

            #pragma unroll 4
            for (int c = 0; c < C; c++) {
                float4 w4 = *(const float4*)(sWt + (c << 7) + 4 * tx);
                const int X = c & 0x1C;
                const float* hc = sh + (c << 5);
                ulonglong2 hA = *(const ulonglong2*)(hc + ((ty8 + 0) ^ X));
                ulonglong2 hB = *(const ulonglong2*)(hc + ((ty8 + 4) ^ X));
                u64 q0 = rep2(w4.x), q1 = rep2(w4.y), q2 = rep2(w4.z), q3 = rep2(w4.w);
                acc[0][0] = fma2(q0, hA.x, acc[0][0]);
                acc[0][1] = fma2(q0, hA.y, acc[0][1]);
                acc[0][2] = fma2(q0, hB.x, acc[0][2]);
                acc[0][3] = fma2(q0, hB.y, acc[0][3]);
                acc[1][0] = fma2(q1, hA.x, acc[1][0]);
                acc[1][1] = fma2(q1, hA.y, acc[1][1]);
                acc[1][2] = fma2(q1, hB.x, acc[1][2]);
                acc[1][3] = fma2(q1, hB.y, acc[1][3]);
                acc[2][0] = fma2(q2, hA.x, acc[2][0]);
                acc[2][1] = fma2(q2, hA.y, acc[2][1]);
                acc[2][2] = fma2(q2, hB.x, acc[2][2]);
                acc[2][3] = fma2(q2, hB.y, acc[2][3]);
                acc[3][0] = fma2(q3, hA.x, acc[3][0]);
                acc[3][1] = fma2(q3, hA.y, acc[3][1]);
                acc[3][2] = fma2(q3, hB.x, acc[3][2]);
                acc[3][3] = fma2(q3, hB.y, acc[3][3]);
            }
            bar_arrive(3 + s);              // stage free (acc lives in regs)

            #pragma unroll
            for (int pp = 0; pp < 4; pp++) {
                float2 a0 = unpack2(acc[0][pp]);
                float2 a1 = unpack2(acc[1][pp]);
                float2 a2 = unpack2(acc[2][pp]);
                float2 a3 = unpack2(acc[3][pp]);
                float4 o0, o1;
                o0.x = fmaxf(a0.x + b4.x, 0.f);
                o0.y = fmaxf(a1.x + b4.y, 0.f);
                o0.z = fmaxf(a2.x + b4.z, 0.f);
                o0.w = fmaxf(a3.x + b4.w, 0.f);
                o1.x = fmaxf(a0.y + b4.x, 0.f);
                o1.y = fmaxf(a1.y + b4.y, 0.f);
                o1.z = fmaxf(a2.y + b4.z, 0.f);
                o1.w = fmaxf(a3.y + b4.w, 0.f);
                const size_t rbase = (size_t)(row0 + ty8 + 2 * pp) * C + 4 * tx;
                *(float4*)(out + rbase)     = o0;
                *(float4*)(out + rbase + C) = o1;
            }
        }
    }
}

extern "C" void kernel_launch(void* const* d_in, const int* in_sizes, int n_in,
                              void* d_out, int out_size)
{
    const float* x    = (const float*)d_in[0];
    const void*  ei   = d_in[1];
    const float* W    = (const float*)d_in[2];
    const float* bias = (const float*)d_in[3];
    const float* eps  = (const float*)d_in[4];
    float*       out  = (float*)d_out;

    cudaFuncSetAttribute(gin_fused_kernel,
                         cudaFuncAttributeMaxDynamicSharedMemorySize, SMEM_BYTES);

    gin_fused_kernel<<<GRID, THREADS, SMEM_BYTES>>>(x, ei, W, bias, eps, out);
}